// round 1
// baseline (speedup 1.0000x reference)
#include <cuda_runtime.h>
#include <cuda_bf16.h>

#define BATCH 4096
#define NHID  512
#define BR    32

// One block per sample. 3 warps, warp d computes level d:
//   logits[c] = sum_h x[h] * W[node_d][h][c]   (lane = c)
// then warp softmax over 32 lanes, pick step prob, product across levels.
__global__ __launch_bounds__(96, 16)
void hs_kernel(const float* __restrict__ x,
               const int* __restrict__ labels,
               const float* __restrict__ W,
               float* __restrict__ out)
{
    __shared__ float xs[NHID];
    __shared__ float pshared[3];

    const int b    = blockIdx.x;
    const int tid  = threadIdx.x;
    const int warp = tid >> 5;
    const int lane = tid & 31;

    // Stage this sample's input vector in smem (vectorized: 512 floats = 128 float4)
    {
        const float4* xg = reinterpret_cast<const float4*>(x + (size_t)b * NHID);
        float4* xsv = reinterpret_cast<float4*>(xs);
        for (int i = tid; i < NHID / 4; i += 96) xsv[i] = xg[i];
    }
    __syncthreads();

    const int lab = labels[b];

    // Per-level node index and step (BR=32 -> pure shifts/masks)
    int node, step;
    if (warp == 0)      { node = 0;                 step = lab >> 10; }
    else if (warp == 1) { node = 1  + (lab >> 10);  step = (lab >> 5) & 31; }
    else                { node = 33 + (lab >> 5);   step = lab & 31; }

    // Lane 'lane' walks column 'lane' of W[node]: stride 32 floats = 128B rows,
    // warp-coalesced (one 128B line per h).
    const float* __restrict__ Wn = W + (size_t)node * (NHID * BR) + lane;

    float a0 = 0.f, a1 = 0.f, a2 = 0.f, a3 = 0.f;
    #pragma unroll 4
    for (int h = 0; h < NHID; h += 4) {
        a0 = fmaf(xs[h + 0], __ldg(Wn + (h + 0) * BR), a0);
        a1 = fmaf(xs[h + 1], __ldg(Wn + (h + 1) * BR), a1);
        a2 = fmaf(xs[h + 2], __ldg(Wn + (h + 2) * BR), a2);
        a3 = fmaf(xs[h + 3], __ldg(Wn + (h + 3) * BR), a3);
    }
    float logit = (a0 + a1) + (a2 + a3);

    // Warp softmax over 32 columns
    float m = logit;
    #pragma unroll
    for (int o = 16; o; o >>= 1) m = fmaxf(m, __shfl_xor_sync(0xffffffffu, m, o));
    float e = __expf(logit - m);
    float s = e;
    #pragma unroll
    for (int o = 16; o; o >>= 1) s += __shfl_xor_sync(0xffffffffu, s, o);

    // Probability at this level's step column
    float pstep = __shfl_sync(0xffffffffu, e, step) / s;

    if (lane == 0) pshared[warp] = pstep;
    __syncthreads();
    if (tid == 0) out[b] = pshared[0] * pshared[1] * pshared[2];
}

extern "C" void kernel_launch(void* const* d_in, const int* in_sizes, int n_in,
                              void* d_out, int out_size)
{
    const float* x      = (const float*)d_in[0];   // inputs [4096, 512] f32
    const int*   labels = (const int*)d_in[1];     // labels [4096] i32
    const float* W      = (const float*)d_in[2];   // W [1057, 512, 32] f32
    float*       out    = (float*)d_out;           // [4096] f32

    hs_kernel<<<BATCH, 96>>>(x, labels, W, out);
}